// round 11
// baseline (speedup 1.0000x reference)
#include <cuda_runtime.h>

#define SS   21      // search size
#define PAD  10
#define BS   4       // block size
#define TILE 24      // rows: BS + SS - 1
#define TC   28      // tile cols: 2*BS + SS - 1 (pitch)
#define H    256
#define W    256

__global__ __launch_bounds__(96, 14)
void pred_kernel(const float* __restrict__ im1,
                 const float* __restrict__ im2,
                 float* __restrict__ out)
{
    __shared__ __align__(16) float im2t[TILE * TC];   // 24 x 28
    __shared__ float im1t[32];          // 2 sub-blocks x 16
    __shared__ float red[2][16][21];    // [sub][pixel][i] partial weighted sums
    __shared__ float sg[2][21];         // [sub][i] lane-local weight-sums
    __shared__ float sm[2][21];         // [sub][i] lane-local vol minima

    const int t  = threadIdx.x;
    const int bx = blockIdx.x, by = blockIdx.y, b = blockIdx.z;
    const float* i1 = im1 + b * H * W;
    const float* i2 = im2 + b * H * W;

    const int x0 = bx * (2 * BS) - PAD;   // even
    const int y0 = by * BS - PAD;

    // ---- Phase 0: load 24x28 im2 halo tile (shared by both sub-blocks) ----
    if (bx >= 2 && bx <= 29 && by >= 3 && by <= 60) {
        // interior: coalesced float2 (x0 even). 336 float2 over 96 threads.
        #pragma unroll
        for (int p = 0; p < 4; p++) {
            int idx = t + p * 96;
            if (idx < TILE * (TC / 2)) {
                int r  = idx / (TC / 2);
                int c2 = idx - r * (TC / 2);
                float2 v = *(const float2*)(i2 + (y0 + r) * W + x0 + c2 * 2);
                *(float2*)&im2t[r * TC + c2 * 2] = v;
            }
        }
    } else {
        // border: predicated zero-pad
        #pragma unroll
        for (int q = 0; q < 7; q++) {
            int idx = t + q * 96;
            if (idx < TILE * TC) {
                int r = idx / TC, c = idx - r * TC;
                int y = y0 + r, x = x0 + c;
                float v = 0.0f;
                if ((unsigned)y < (unsigned)H && (unsigned)x < (unsigned)W)
                    v = i2[y * W + x];
                im2t[r * TC + c] = v;
            }
        }
    }
    if (t < 32) {
        int s = t >> 4, w16 = t & 15;
        int py = w16 >> 2, px = w16 & 3;
        im1t[t] = i1[(by * BS + py) * W + bx * (2 * BS) + s * BS + px];
    }
    __syncthreads();

    // ---- mapping: s = sub-block (t/48), u = t%48, i = u>>1, h = u&1 ----
    const int s  = t / 48;
    const int u  = t - s * 48;
    const int i  = u >> 1;            // shift row 0..20
    const int h  = u & 1;             // row-pair selector
    const bool act = (u < 42);
    const int lane = t & 31;
    const unsigned pmask = 3u << (lane & ~1);   // shuffle pair mask

    const unsigned sbA = (unsigned)__cvta_generic_to_shared(
                             &im2t[(2 * h + i) * TC + s * BS]);
    const unsigned sbB = sbA + TC * 4u;   // next row

    float vol[SS];
    float lmin = 1e30f;

    // ---- Phase 1: 2-row SADs with sliding-window loads, pair-reduce, local min
    if (act) {
        const float* ap = &im1t[s * 16 + 2 * h * 4];
        const float a0 = ap[0], a1 = ap[1], a2 = ap[2], a3 = ap[3];
        const float b0 = ap[4], b1 = ap[5], b2 = ap[6], b3 = ap[7];
        float rA[TILE], rB[TILE];
        #pragma unroll
        for (int g = 0; g < 6; g++) {
            float4 va = ((const float4*)__cvta_shared_to_generic((size_t)sbA))[g];
            float4 vb = ((const float4*)__cvta_shared_to_generic((size_t)sbB))[g];
            rA[4*g] = va.x; rA[4*g+1] = va.y; rA[4*g+2] = va.z; rA[4*g+3] = va.w;
            rB[4*g] = vb.x; rB[4*g+1] = vb.y; rB[4*g+2] = vb.z; rB[4*g+3] = vb.w;
            if (g >= 1) {
                #pragma unroll
                for (int jj = 0; jj < 4; jj++) {
                    int j = 4 * (g - 1) + jj;
                    vol[j] = fabsf(a0 - rA[j])     + fabsf(a1 - rA[j + 1])
                           + fabsf(a2 - rA[j + 2]) + fabsf(a3 - rA[j + 3])
                           + fabsf(b0 - rB[j])     + fabsf(b1 - rB[j + 1])
                           + fabsf(b2 - rB[j + 2]) + fabsf(b3 - rB[j + 3]);
                }
            }
        }
        vol[20] = fabsf(a0 - rA[20]) + fabsf(a1 - rA[21])
                + fabsf(a2 - rA[22]) + fabsf(a3 - rA[23])
                + fabsf(b0 - rB[20]) + fabsf(b1 - rB[21])
                + fabsf(b2 - rB[22]) + fabsf(b3 - rB[23]);

        // single-step pair allreduce over h (pair lanes end identical)
        #pragma unroll
        for (int j = 0; j < SS; j++)
            vol[j] += __shfl_xor_sync(pmask, vol[j], 1);

        // lane-local min — NO CTA-wide reduction, NO barrier needed before use
        lmin = vol[0];
        #pragma unroll
        for (int j = 1; j < SS; j++) lmin = fminf(lmin, vol[j]);
        if (h == 0) sm[s][i] = lmin;    // for phase-4 rescale
    }

    // ---- Phase 3: fused weights (local offset) + 2-row accumulation ----
    if (act) {
        // w = 2^(K*vol + M), K = -6.25*log2(e), M = -K*lmin  (lane-local!)
        const float K = -9.016844005555897f;
        const float M = -K * lmin;
        float lsum = 0.0f;
        float c0 = 0.f, c1 = 0.f, c2 = 0.f, c3 = 0.f;   // pixel row 2h
        float d0 = 0.f, d1 = 0.f, d2 = 0.f, d3 = 0.f;   // pixel row 2h+1
        float rA[TILE], rB[TILE];
        #pragma unroll
        for (int g = 0; g < 6; g++) {
            asm volatile("ld.shared.v4.f32 {%0,%1,%2,%3}, [%4];"
                : "=f"(rA[4*g]), "=f"(rA[4*g+1]), "=f"(rA[4*g+2]), "=f"(rA[4*g+3])
                : "r"(sbA + 16u * g));
            asm volatile("ld.shared.v4.f32 {%0,%1,%2,%3}, [%4];"
                : "=f"(rB[4*g]), "=f"(rB[4*g+1]), "=f"(rB[4*g+2]), "=f"(rB[4*g+3])
                : "r"(sbB + 16u * g));
            if (g >= 1) {
                #pragma unroll
                for (int jj = 0; jj < 4; jj++) {
                    int j = 4 * (g - 1) + jj;
                    float e = fmaf(vol[j], K, M);
                    float wv;
                    asm("ex2.approx.ftz.f32 %0, %1;" : "=f"(wv) : "f"(e));
                    lsum += wv;
                    c0 = fmaf(wv, rA[j],     c0);
                    c1 = fmaf(wv, rA[j + 1], c1);
                    c2 = fmaf(wv, rA[j + 2], c2);
                    c3 = fmaf(wv, rA[j + 3], c3);
                    d0 = fmaf(wv, rB[j],     d0);
                    d1 = fmaf(wv, rB[j + 1], d1);
                    d2 = fmaf(wv, rB[j + 2], d2);
                    d3 = fmaf(wv, rB[j + 3], d3);
                }
            }
        }
        {
            float e = fmaf(vol[20], K, M);
            float wv;
            asm("ex2.approx.ftz.f32 %0, %1;" : "=f"(wv) : "f"(e));
            lsum += wv;
            c0 = fmaf(wv, rA[20], c0); c1 = fmaf(wv, rA[21], c1);
            c2 = fmaf(wv, rA[22], c2); c3 = fmaf(wv, rA[23], c3);
            d0 = fmaf(wv, rB[20], d0); d1 = fmaf(wv, rB[21], d1);
            d2 = fmaf(wv, rB[22], d2); d3 = fmaf(wv, rB[23], d3);
        }
        if (h == 0) sg[s][i] = lsum;     // pair lanes hold identical lsum
        const int pr = 2 * h * 4;
        red[s][pr + 0][i] = c0;  red[s][pr + 1][i] = c1;
        red[s][pr + 2][i] = c2;  red[s][pr + 3][i] = c3;
        red[s][pr + 4][i] = d0;  red[s][pr + 5][i] = d1;
        red[s][pr + 6][i] = d2;  red[s][pr + 7][i] = d3;
    }
    __syncthreads();

    // ---- Phase 4: rescale-merge over 21 shift-rows, normalize, store ----
    if (t < 32) {
        int so = t >> 4, tt = t & 15;
        const float K = -9.016844005555897f;
        // global offset for this sub-block
        float mstar = sm[so][0];
        #pragma unroll
        for (int q = 1; q < SS; q++) mstar = fminf(mstar, sm[so][q]);
        float sum = 0.0f, ws = 0.0f;
        #pragma unroll
        for (int q = 0; q < SS; q++) {
            float e = K * (sm[so][q] - mstar);   // <= 0
            float sc;
            asm("ex2.approx.ftz.f32 %0, %1;" : "=f"(sc) : "f"(e));
            sum = fmaf(sc, red[so][tt][q], sum);
            ws  = fmaf(sc, sg[so][q],      ws);
        }
        int py2 = tt >> 2, px2 = tt & 3;
        out[b * H * W + (by * BS + py2) * W + bx * (2 * BS) + so * BS + px2]
            = sum / ws;
    }
}

extern "C" void kernel_launch(void* const* d_in, const int* in_sizes, int n_in,
                              void* d_out, int out_size) {
    const float* im1 = (const float*)d_in[0];
    const float* im2 = (const float*)d_in[1];
    float* out = (float*)d_out;
    dim3 grid(W / (2 * BS), H / BS, 2);   // (32, 64, 2)
    pred_kernel<<<grid, 96>>>(im1, im2, out);
}

// round 12
// speedup vs baseline: 1.0171x; 1.0171x over previous
#include <cuda_runtime.h>

#define SS   21      // search size
#define PAD  10
#define BS   4       // block size
#define TILE 24      // rows: BS + SS - 1
#define TC   28      // tile cols: 2*BS + SS - 1 (pitch)
#define H    256
#define W    256

__global__ __launch_bounds__(96, 14)
void pred_kernel(const float* __restrict__ im1,
                 const float* __restrict__ im2,
                 float* __restrict__ out)
{
    __shared__ __align__(16) float im2t[TILE * TC];   // 24 x 28
    __shared__ __align__(16) float im1t[32];          // 4 rows x 8 cols (both subs)
    __shared__ __align__(16) float red[2][21][16];    // [sub][i][pixel] weighted sums
    __shared__ float smsg[2][21][2];                  // [sub][i][{min,lsum}]

    const int t  = threadIdx.x;
    const int bx = blockIdx.x, by = blockIdx.y, b = blockIdx.z;
    const float* i1 = im1 + b * H * W;
    const float* i2 = im2 + b * H * W;

    const int x0 = bx * (2 * BS) - PAD;   // even
    const int y0 = by * BS - PAD;

    // ---- Phase 0: load 24x28 im2 halo tile (shared by both sub-blocks) ----
    if (bx >= 2 && bx <= 29 && by >= 3 && by <= 60) {
        // interior: coalesced float2 (x0 even). 336 float2 over 96 threads.
        #pragma unroll
        for (int p = 0; p < 4; p++) {
            int idx = t + p * 96;
            if (idx < TILE * (TC / 2)) {
                int r  = idx / (TC / 2);
                int c2 = idx - r * (TC / 2);
                float2 v = *(const float2*)(i2 + (y0 + r) * W + x0 + c2 * 2);
                *(float2*)&im2t[r * TC + c2 * 2] = v;
            }
        }
    } else {
        // border: predicated zero-pad
        #pragma unroll
        for (int q = 0; q < 7; q++) {
            int idx = t + q * 96;
            if (idx < TILE * TC) {
                int r = idx / TC, c = idx - r * TC;
                int y = y0 + r, x = x0 + c;
                float v = 0.0f;
                if ((unsigned)y < (unsigned)H && (unsigned)x < (unsigned)W)
                    v = i2[y * W + x];
                im2t[r * TC + c] = v;
            }
        }
    }
    if (t < 8) {
        // im1 4x8 block (both sub-blocks), 16B-aligned vector loads
        int r = t >> 1, q = t & 1;
        float4 v = *(const float4*)(i1 + (by * BS + r) * W + bx * (2 * BS) + q * 4);
        *(float4*)&im1t[r * 8 + q * 4] = v;
    }
    __syncthreads();

    // ---- mapping: s = sub-block (t/48), u = t%48, i = u>>1, h = u&1 ----
    const int s  = t / 48;
    const int u  = t - s * 48;
    const int i  = u >> 1;            // shift row 0..20
    const int h  = u & 1;             // row-pair selector
    const bool act = (u < 42);
    const int lane = t & 31;
    const unsigned pmask = 3u << (lane & ~1);   // shuffle pair mask

    const unsigned sbA = (unsigned)__cvta_generic_to_shared(
                             &im2t[(2 * h + i) * TC + s * BS]);
    const unsigned sbB = sbA + TC * 4u;   // next row

    float vol[SS];
    float lmin = 1e30f;

    // ---- Phase 1: 2-row SADs with sliding-window loads, pair-reduce, local min
    if (act) {
        const float* ap = &im1t[2 * h * 8 + s * BS];
        const float a0 = ap[0], a1 = ap[1], a2 = ap[2], a3 = ap[3];
        const float b0 = ap[8], b1 = ap[9], b2 = ap[10], b3 = ap[11];
        float rA[TILE], rB[TILE];
        #pragma unroll
        for (int g = 0; g < 6; g++) {
            float4 va = ((const float4*)__cvta_shared_to_generic((size_t)sbA))[g];
            float4 vb = ((const float4*)__cvta_shared_to_generic((size_t)sbB))[g];
            rA[4*g] = va.x; rA[4*g+1] = va.y; rA[4*g+2] = va.z; rA[4*g+3] = va.w;
            rB[4*g] = vb.x; rB[4*g+1] = vb.y; rB[4*g+2] = vb.z; rB[4*g+3] = vb.w;
            if (g >= 1) {
                #pragma unroll
                for (int jj = 0; jj < 4; jj++) {
                    int j = 4 * (g - 1) + jj;
                    vol[j] = fabsf(a0 - rA[j])     + fabsf(a1 - rA[j + 1])
                           + fabsf(a2 - rA[j + 2]) + fabsf(a3 - rA[j + 3])
                           + fabsf(b0 - rB[j])     + fabsf(b1 - rB[j + 1])
                           + fabsf(b2 - rB[j + 2]) + fabsf(b3 - rB[j + 3]);
                }
            }
        }
        vol[20] = fabsf(a0 - rA[20]) + fabsf(a1 - rA[21])
                + fabsf(a2 - rA[22]) + fabsf(a3 - rA[23])
                + fabsf(b0 - rB[20]) + fabsf(b1 - rB[21])
                + fabsf(b2 - rB[22]) + fabsf(b3 - rB[23]);

        // single-step pair allreduce over h (pair lanes end identical)
        #pragma unroll
        for (int j = 0; j < SS; j++)
            vol[j] += __shfl_xor_sync(pmask, vol[j], 1);

        // lane-local min — no CTA-wide reduction needed
        lmin = vol[0];
        #pragma unroll
        for (int j = 1; j < SS; j++) lmin = fminf(lmin, vol[j]);
        if (h == 0) smsg[s][i][0] = lmin;    // for phase-4 rescale
    }

    // ---- Phase 3: fused weights (local offset) + 2-row accumulation ----
    if (act) {
        // w = 2^(K*vol + M), K = -6.25*log2(e), M = -K*lmin (lane-local)
        const float K = -9.016844005555897f;
        const float M = -K * lmin;
        float lsum = 0.0f;
        float c0 = 0.f, c1 = 0.f, c2 = 0.f, c3 = 0.f;   // pixel row 2h
        float d0 = 0.f, d1 = 0.f, d2 = 0.f, d3 = 0.f;   // pixel row 2h+1
        float rA[TILE], rB[TILE];
        #pragma unroll
        for (int g = 0; g < 6; g++) {
            asm volatile("ld.shared.v4.f32 {%0,%1,%2,%3}, [%4];"
                : "=f"(rA[4*g]), "=f"(rA[4*g+1]), "=f"(rA[4*g+2]), "=f"(rA[4*g+3])
                : "r"(sbA + 16u * g));
            asm volatile("ld.shared.v4.f32 {%0,%1,%2,%3}, [%4];"
                : "=f"(rB[4*g]), "=f"(rB[4*g+1]), "=f"(rB[4*g+2]), "=f"(rB[4*g+3])
                : "r"(sbB + 16u * g));
            if (g >= 1) {
                #pragma unroll
                for (int jj = 0; jj < 4; jj++) {
                    int j = 4 * (g - 1) + jj;
                    float e = fmaf(vol[j], K, M);
                    float wv;
                    asm("ex2.approx.ftz.f32 %0, %1;" : "=f"(wv) : "f"(e));
                    lsum += wv;
                    c0 = fmaf(wv, rA[j],     c0);
                    c1 = fmaf(wv, rA[j + 1], c1);
                    c2 = fmaf(wv, rA[j + 2], c2);
                    c3 = fmaf(wv, rA[j + 3], c3);
                    d0 = fmaf(wv, rB[j],     d0);
                    d1 = fmaf(wv, rB[j + 1], d1);
                    d2 = fmaf(wv, rB[j + 2], d2);
                    d3 = fmaf(wv, rB[j + 3], d3);
                }
            }
        }
        {
            float e = fmaf(vol[20], K, M);
            float wv;
            asm("ex2.approx.ftz.f32 %0, %1;" : "=f"(wv) : "f"(e));
            lsum += wv;
            c0 = fmaf(wv, rA[20], c0); c1 = fmaf(wv, rA[21], c1);
            c2 = fmaf(wv, rA[22], c2); c3 = fmaf(wv, rA[23], c3);
            d0 = fmaf(wv, rB[20], d0); d1 = fmaf(wv, rB[21], d1);
            d2 = fmaf(wv, rB[22], d2); d3 = fmaf(wv, rB[23], d3);
        }
        if (h == 0) smsg[s][i][1] = lsum;    // pair lanes hold identical lsum
        // contiguous vector stores: [pixel rows 2h (c) and 2h+1 (d)]
        *(float4*)&red[s][i][8 * h]     = make_float4(c0, c1, c2, c3);
        *(float4*)&red[s][i][8 * h + 4] = make_float4(d0, d1, d2, d3);
    }
    __syncthreads();

    // ---- Phase 4: split rescale-merge over 21 shift-rows (64 threads) ----
    // warp so handles sub-block so; half-warps split the q range.
    if (t < 64) {
        const int so   = t >> 5;
        const int half = (t >> 4) & 1;
        const int tt   = t & 15;
        const int q0   = half ? 11 : 0;
        const int qn   = half ? 10 : 11;
        const float K  = -9.016844005555897f;

        // local min over own half
        float mh = 1e30f;
        for (int q = 0; q < qn; q++)
            mh = fminf(mh, smsg[so][q0 + q][0]);
        // global offset via cross-half shuffle
        float mstar = fminf(mh, __shfl_xor_sync(0xffffffffu, mh, 16));

        float sum = 0.0f, ws = 0.0f;
        for (int q = 0; q < qn; q++) {
            float2 msv = *(const float2*)&smsg[so][q0 + q][0];
            float e = K * (msv.x - mstar);   // <= 0
            float sc;
            asm("ex2.approx.ftz.f32 %0, %1;" : "=f"(sc) : "f"(e));
            sum = fmaf(sc, red[so][q0 + q][tt], sum);
            ws  = fmaf(sc, msv.y,               ws);
        }
        sum += __shfl_xor_sync(0xffffffffu, sum, 16);
        ws  += __shfl_xor_sync(0xffffffffu, ws, 16);

        if (half == 0) {
            int py2 = tt >> 2, px2 = tt & 3;
            out[b * H * W + (by * BS + py2) * W + bx * (2 * BS) + so * BS + px2]
                = __fdividef(sum, ws);
        }
    }
}

extern "C" void kernel_launch(void* const* d_in, const int* in_sizes, int n_in,
                              void* d_out, int out_size) {
    const float* im1 = (const float*)d_in[0];
    const float* im2 = (const float*)d_in[1];
    float* out = (float*)d_out;
    dim3 grid(W / (2 * BS), H / BS, 2);   // (32, 64, 2)
    pred_kernel<<<grid, 96>>>(im1, im2, out);
}